// round 14
// baseline (speedup 1.0000x reference)
#include <cuda_runtime.h>
#include <math.h>

// ---------------------------------------------------------------------------
// 2-layer LSTM, B=16, S=2048, I=256, H=512, fp32.
// Persistent kernel, 128 CTAs (1/SM), 512 threads = 2 warp groups.
//   Group A (tid 0..255):  h0 recurrence: poll f0 -> stage [x|h0] -> GEMM0
//                          -> cell0 -> publish f0.
//   Group B (tid 256..511): GEMM1 (h0-half, signal slot-free, h1-half)
//                          -> cell1 -> publish f1 -> out.
// GEMM1 overlaps the h0 recurrence on separate warps. Cross-group sync via
// two monotone smem mailboxes; per-group named barriers only.
// Packed row-pair GEMM from R12 (k-major W, FFMA2 over 2 rows, 64 regs acc).
// ---------------------------------------------------------------------------

#define BATCH 16
#define SEQ   2048
#define IDIM  256
#define HDIM  512
#define NCTA  128
#define NTHREADS 512
#define ROWS  16
#define UNITS 4
#define K0    768
#define K1    1024
#define WP    18          // k-major weight pitch
#define PA    1282        // A pitch [x:256 | h0:512 | h1:512], 8*PA%32==16
#define SP    20          // slab pitch (col-major)
#define SLABSZ (16*SP)    // 320 floats per warp slab

typedef unsigned long long ull;

// ---- global scratch ----
__device__ __align__(16) float g_h0[2][BATCH * HDIM];
__device__ __align__(16) float g_h1[2][BATCH * HDIM];
__device__ unsigned int g_f0[NCTA];
__device__ unsigned int g_f1[NCTA];
__device__ unsigned int g_bar_count = 0;
__device__ volatile unsigned int g_bar_epoch = 0;

__device__ __forceinline__ unsigned int ld_acq(const unsigned int* p) {
    unsigned int v;
    asm volatile("ld.acquire.gpu.u32 %0, [%1];" : "=r"(v) : "l"(p) : "memory");
    return v;
}
__device__ __forceinline__ void st_rel(unsigned int* p, unsigned int v) {
    asm volatile("st.release.gpu.u32 [%0], %1;" :: "l"(p), "r"(v) : "memory");
}

__device__ __forceinline__ void entry_barrier() {
    unsigned int ebase = 0;
    if (threadIdx.x == 0) ebase = g_bar_epoch;
    __syncthreads();
    if (threadIdx.x == 0) {
        __threadfence();
        unsigned int a = atomicAdd(&g_bar_count, 1u);
        unsigned int target = ebase + 1;
        if (a == NCTA - 1) {
            atomicExch(&g_bar_count, 0u);
            __threadfence();
            g_bar_epoch = target;
        } else {
            while ((int)(g_bar_epoch - target) < 0) { }
        }
        __threadfence();
    }
    __syncthreads();
}

// ---- packed f32x2 helpers ----
__device__ __forceinline__ void ffma2(ull& acc, ull a, ull b) {
    asm("fma.rn.f32x2 %0, %1, %2, %0;" : "+l"(acc) : "l"(a), "l"(b));
}
__device__ __forceinline__ ull dup2(float a) {
    ull r;
    asm("mov.b64 %0, {%1, %1};" : "=l"(r) : "f"(a));
    return r;
}
__device__ __forceinline__ void unpack2(ull v, float& lo, float& hi) {
    asm("mov.b64 {%0, %1}, %2;" : "=f"(lo), "=f"(hi) : "l"(v));
}

// ---- fast activations (MUFU; validated rel_err ~2e-6) ----
__device__ __forceinline__ float fsig(float x) {
    float e, r;
    asm("ex2.approx.f32 %0, %1;" : "=f"(e) : "f"(-1.4426950408889634f * x));
    asm("rcp.approx.f32 %0, %1;" : "=f"(r) : "f"(1.0f + e));
    return r;
}
__device__ __forceinline__ float ftanh(float x) {
    float e, r;
    asm("ex2.approx.f32 %0, %1;" : "=f"(e) : "f"(-2.8853900817779268f * x));
    asm("rcp.approx.f32 %0, %1;" : "=f"(r) : "f"(1.0f + e));
    return 2.0f * r - 1.0f;
}

// ---- packed GEMM over a 256-thread group; ltid = tid&255 ----
// kg = ltid>>2 (0..63 split-K), tr=(ltid>>1)&1, tc=ltid&1.
// Per k: 4 LDS.64 (W row-pairs) + 8 LDS.32 (A) + 8 dup + 32 FFMA2.
template <int NQ>
__device__ __forceinline__ void gemm_packed(const float* __restrict__ sWt,
                                            const float* __restrict__ sA,
                                            ull acc[4][8], int ltid) {
    const int kg = ltid >> 2;
    const int tr = (ltid >> 1) & 1;
    const int tc = ltid & 1;
    const float* wb = sWt + kg * WP + 8 * tr;
    const float* ab = sA + (8 * tc) * PA + kg;

#pragma unroll 1
    for (int q = 0; q < NQ; ++q) {
        const float* w = wb + q * (64 * WP);
        const float* a = ab + q * 64;
        float av[8];
#pragma unroll
        for (int j = 0; j < 8; ++j) av[j] = a[j * PA];
        ull ad[8];
#pragma unroll
        for (int j = 0; j < 8; ++j) ad[j] = dup2(av[j]);
        ull wv[4];
#pragma unroll
        for (int rp = 0; rp < 4; ++rp) wv[rp] = *(const ull*)(w + 2 * rp);
#pragma unroll
        for (int rp = 0; rp < 4; ++rp)
#pragma unroll
            for (int j = 0; j < 8; ++j)
                ffma2(acc[rp][j], wv[rp], ad[j]);
    }
}

// 3-level xor-shuffle (kg within warp) -> warp slab (col-major, pitch SP)
__device__ __forceinline__ void reduce_store(ull acc[4][8],
                                             float* __restrict__ slab,
                                             int ltid) {
    const int lane = ltid & 31;
    const int tr = (ltid >> 1) & 1;
    const int tc = ltid & 1;
    const bool st = (lane & 28) == 0;
#pragma unroll
    for (int rp = 0; rp < 4; ++rp)
#pragma unroll
        for (int j = 0; j < 8; ++j) {
            float lo, hi;
            unpack2(acc[rp][j], lo, hi);
            lo += __shfl_xor_sync(0xffffffffu, lo, 4);
            hi += __shfl_xor_sync(0xffffffffu, hi, 4);
            lo += __shfl_xor_sync(0xffffffffu, lo, 8);
            hi += __shfl_xor_sync(0xffffffffu, hi, 8);
            lo += __shfl_xor_sync(0xffffffffu, lo, 16);
            hi += __shfl_xor_sync(0xffffffffu, hi, 16);
            if (st) {
                float* d = slab + (8 * tc + j) * SP + 8 * tr + 2 * rp;
                d[0] = lo;
                d[1] = hi;
            }
        }
}

#define BARA() asm volatile("bar.sync 1, 256;" ::: "memory")
#define BARB() asm volatile("bar.sync 2, 256;" ::: "memory")

__global__ void __launch_bounds__(NTHREADS, 1)
lstm2_persistent(const float* __restrict__ x,
                 const float* __restrict__ W0,
                 const float* __restrict__ b0,
                 const float* __restrict__ W1,
                 const float* __restrict__ b1,
                 float* __restrict__ out) {
    extern __shared__ float smem[];
    float* sW0t = smem;                     // 768*18
    float* sW1t = sW0t + K0 * WP;           // 1024*18
    float* sA   = sW1t + K1 * WP;           // 16*1282  [x | h0 | h1]
    float* sSlA = sA + BATCH * PA;          // 8*320  group A slabs
    float* sSlB = sSlA + 8 * SLABSZ;        // 8*320  group B slabs
    float* sB0  = sSlB + 8 * SLABSZ;        // 16
    float* sB1  = sB0 + 16;                 // 16
    volatile int* sMail = (volatile int*)(sB1 + 16);  // [0]=h0Ready [1]=slotFree

    const int m    = blockIdx.x;
    const int tid  = threadIdx.x;
    const int ltid = tid & 255;
    const int grp  = tid >> 8;              // 0 = A, 1 = B
    const int u0   = m * UNITS;

    // ---- one-time setup (all 512 threads) ----
    for (int idx = tid; idx < ROWS * K0; idx += NTHREADS) {
        int r = idx / K0, k = idx % K0;
        int gg = r & 3, u = r >> 2;
        sW0t[k * WP + r] = W0[(size_t)(gg * HDIM + u0 + u) * K0 + k];
    }
    for (int idx = tid; idx < ROWS * K1; idx += NTHREADS) {
        int r = idx / K1, k = idx % K1;
        int gg = r & 3, u = r >> 2;
        sW1t[k * WP + r] = W1[(size_t)(gg * HDIM + u0 + u) * K1 + k];
    }
    if (tid < ROWS) {
        int gg = tid & 3, u = tid >> 2;
        sB0[tid] = b0[gg * HDIM + u0 + u];
        sB1[tid] = b1[gg * HDIM + u0 + u];
    }
    if (tid == 0) { sMail[0] = -1; sMail[1] = -1; }

    const int uu = ltid >> 4;               // cell role (ltid < 64)
    const int bb = ltid & 15;
    float c0 = 0.f, c1 = 0.f, h0r = 0.f, h1r = 0.f;

    const unsigned int fbase = g_f0[m];     // replay-safe (== g_f1[m])

    if (tid < 64) g_h0[1][bb * HDIM + u0 + uu] = 0.f;          // h0(-1)
    if (grp == 1 && ltid < 64) g_h1[1][bb * HDIM + u0 + uu] = 0.f;  // h1(-1)
    entry_barrier();

    ull acc[4][8];

    if (grp == 0) {
        // ================= GROUP A: h0 recurrence =================
        for (int i = 0; i <= SEQ; ++i) {
            const unsigned int seq = fbase + (unsigned)i;

            // stage x(i)
            if (i < SEQ) {
                const float* xrow = x + (size_t)i * IDIM;
                for (int idx = ltid; idx < BATCH * (IDIM / 2); idx += 256) {
                    int b = idx >> 7, k = (idx & 127) * 2;
                    *(float2*)(sA + b * PA + k) =
                        *(const float2*)(xrow + (size_t)b * SEQ * IDIM + k);
                }
            }
            // hot poll h0(i-1) + slot-free from B
            if (ltid < 128) {
                while ((int)(ld_acq(&g_f0[ltid]) - seq) < 0) { }
            } else if (ltid == 128 && i >= 2) {
                while (sMail[1] < i - 1) { }
            }
            BARA();
            // stage h0(i-1) into slot
            {
                const float* src = g_h0[(i + 1) & 1];
                for (int idx = ltid; idx < BATCH * (HDIM / 2); idx += 256) {
                    int b = idx >> 8, k = (idx & 255) * 2;
                    float2 v = __ldcg((const float2*)(src + b * HDIM + k));
                    *(float2*)(sA + b * PA + IDIM + k) = v;
                }
            }
            BARA();
            if (ltid == 0) sMail[0] = i;            // h0 slot ready
            // GEMM0 + cell0
            if (i < SEQ) {
#pragma unroll
                for (int a = 0; a < 4; ++a)
#pragma unroll
                    for (int b = 0; b < 8; ++b) acc[a][b] = 0ull;
                gemm_packed<12>(sW0t, sA, acc, ltid);
                reduce_store(acc, sSlA + (ltid >> 5) * SLABSZ, ltid);
                BARA();
                if (ltid < 64) {
                    const float* base = sSlA + bb * SP + 4 * uu;
                    float4 s = *(const float4*)(sB0 + 4 * uu);
#pragma unroll
                    for (int w = 0; w < 8; ++w) {
                        float4 v = *(const float4*)(base + w * SLABSZ);
                        s.x += v.x; s.y += v.y; s.z += v.z; s.w += v.w;
                    }
                    float ig = fsig(s.x), fg = fsig(s.y);
                    float cg = ftanh(s.z), og = fsig(s.w);
                    c0  = fg * c0 + ig * cg;
                    h0r = og * ftanh(c0);
                    g_h0[i & 1][bb * HDIM + u0 + uu] = h0r;
                    asm volatile("bar.sync 5, 64;" ::: "memory");
                    if (ltid == 0) st_rel(&g_f0[m], seq + 1u);
                }
            }
        }
        if (ltid < 64) {
            const size_t OH = (size_t)BATCH * SEQ * HDIM;
            const size_t BH = (size_t)BATCH * HDIM;
            const size_t o  = (size_t)bb * HDIM + u0 + uu;
            out[OH + 0 * BH + o] = h0r;     // h layer 0
            out[OH + 2 * BH + o] = c0;      // c layer 0
        }
    } else {
        // ================= GROUP B: layer 1 =================
        for (int i = 1; i <= SEQ; ++i) {
            const unsigned int seq = fbase + (unsigned)i;

            // cold poll h1(i-2)
            if (ltid < 128) {
                while ((int)(ld_acq(&g_f1[ltid]) - (seq - 1u)) < 0) { }
            }
            BARB();
            // stage h1(i-2)
            {
                const float* src = g_h1[i & 1];
                for (int idx = ltid; idx < BATCH * (HDIM / 2); idx += 256) {
                    int b = idx >> 8, k = (idx & 255) * 2;
                    float2 v = __ldcg((const float2*)(src + b * HDIM + k));
                    *(float2*)(sA + b * PA + IDIM + HDIM + k) = v;
                }
            }
            if (ltid == 0) { while (sMail[0] < i) { } }  // h0 slot ready?
            BARB();
            // GEMM1 part 1: h0 half (k 0..511) -- then release the slot
#pragma unroll
            for (int a = 0; a < 4; ++a)
#pragma unroll
                for (int b = 0; b < 8; ++b) acc[a][b] = 0ull;
            gemm_packed<8>(sW1t, sA + IDIM, acc, ltid);
            BARB();                                   // all h0 reads done
            if (ltid == 0) sMail[1] = i;              // slot free for A
            // GEMM1 part 2: h1 half (k 512..1023)
            gemm_packed<8>(sW1t + HDIM * WP, sA + IDIM + HDIM, acc, ltid);
            reduce_store(acc, sSlB + (ltid >> 5) * SLABSZ, ltid);
            BARB();
            // cell1 + publish h1(i-1) + out
            if (ltid < 64) {
                const float* base = sSlB + bb * SP + 4 * uu;
                float4 s = *(const float4*)(sB1 + 4 * uu);
#pragma unroll
                for (int w = 0; w < 8; ++w) {
                    float4 v = *(const float4*)(base + w * SLABSZ);
                    s.x += v.x; s.y += v.y; s.z += v.z; s.w += v.w;
                }
                float ig = fsig(s.x), fg = fsig(s.y);
                float cg = ftanh(s.z), og = fsig(s.w);
                c1  = fg * c1 + ig * cg;
                h1r = og * ftanh(c1);
                g_h1[(i - 1) & 1][bb * HDIM + u0 + uu] = h1r;
                out[((size_t)bb * SEQ + (i - 1)) * HDIM + u0 + uu] = h1r;
                asm volatile("bar.sync 6, 64;" ::: "memory");
                if (ltid == 0) st_rel(&g_f1[m], seq);
            }
        }
        if (ltid < 64) {
            const size_t OH = (size_t)BATCH * SEQ * HDIM;
            const size_t BH = (size_t)BATCH * HDIM;
            const size_t o  = (size_t)bb * HDIM + u0 + uu;
            out[OH + 1 * BH + o] = h1r;     // h layer 1
            out[OH + 3 * BH + o] = c1;      // c layer 1
        }
    }
}

extern "C" void kernel_launch(void* const* d_in, const int* in_sizes, int n_in,
                              void* d_out, int out_size) {
    const float* x  = (const float*)d_in[0];
    const float* W0 = (const float*)d_in[1];
    const float* b0 = (const float*)d_in[2];
    const float* W1 = (const float*)d_in[3];
    const float* b1 = (const float*)d_in[4];
    float* out = (float*)d_out;

    const int smem_floats = K0 * WP + K1 * WP + BATCH * PA +
                            2 * 8 * SLABSZ + 32 + 8;
    const int smem_bytes = smem_floats * (int)sizeof(float);  // 231,840 B

    cudaFuncSetAttribute(lstm2_persistent,
                         cudaFuncAttributeMaxDynamicSharedMemorySize,
                         smem_bytes);

    lstm2_persistent<<<NCTA, NTHREADS, smem_bytes>>>(x, W0, b0, W1, b1, out);
}

// round 15
// speedup vs baseline: 1.0133x; 1.0133x over previous
#include <cuda_runtime.h>
#include <math.h>

// ---------------------------------------------------------------------------
// 2-layer LSTM, B=16, S=2048, I=256, H=512, fp32.
// Persistent kernel, 128 CTAs (1/SM), 512 threads = 2 warp groups.
//   Group A (tid 0..255):  h0 recurrence: poll f0 -> stage [x|h0] -> GEMM0
//                          -> cell0 -> publish f0.
//   Group B (tid 256..511): GEMM1 (h0-half, signal slot-free, h1-half)
//                          -> cell1 -> publish f1 -> out.
// GEMM1 overlaps the h0 recurrence on separate warps. Cross-group sync via
// two monotone smem mailboxes; per-group named barriers only.
// Packed row-pair GEMM from R12 (k-major W, FFMA2 over 2 rows, 64 regs acc).
// ---------------------------------------------------------------------------

#define BATCH 16
#define SEQ   2048
#define IDIM  256
#define HDIM  512
#define NCTA  128
#define NTHREADS 512
#define ROWS  16
#define UNITS 4
#define K0    768
#define K1    1024
#define WP    18          // k-major weight pitch
#define PA    1282        // A pitch [x:256 | h0:512 | h1:512], 8*PA%32==16
#define SP    20          // slab pitch (col-major)
#define SLABSZ (16*SP)    // 320 floats per warp slab

typedef unsigned long long ull;

// ---- global scratch ----
__device__ __align__(16) float g_h0[2][BATCH * HDIM];
__device__ __align__(16) float g_h1[2][BATCH * HDIM];
__device__ unsigned int g_f0[NCTA];
__device__ unsigned int g_f1[NCTA];
__device__ unsigned int g_bar_count = 0;
__device__ volatile unsigned int g_bar_epoch = 0;

__device__ __forceinline__ unsigned int ld_acq(const unsigned int* p) {
    unsigned int v;
    asm volatile("ld.acquire.gpu.u32 %0, [%1];" : "=r"(v) : "l"(p) : "memory");
    return v;
}
__device__ __forceinline__ void st_rel(unsigned int* p, unsigned int v) {
    asm volatile("st.release.gpu.u32 [%0], %1;" :: "l"(p), "r"(v) : "memory");
}

__device__ __forceinline__ void entry_barrier() {
    unsigned int ebase = 0;
    if (threadIdx.x == 0) ebase = g_bar_epoch;
    __syncthreads();
    if (threadIdx.x == 0) {
        __threadfence();
        unsigned int a = atomicAdd(&g_bar_count, 1u);
        unsigned int target = ebase + 1;
        if (a == NCTA - 1) {
            atomicExch(&g_bar_count, 0u);
            __threadfence();
            g_bar_epoch = target;
        } else {
            while ((int)(g_bar_epoch - target) < 0) { }
        }
        __threadfence();
    }
    __syncthreads();
}

// ---- packed f32x2 helpers ----
__device__ __forceinline__ void ffma2(ull& acc, ull a, ull b) {
    asm("fma.rn.f32x2 %0, %1, %2, %0;" : "+l"(acc) : "l"(a), "l"(b));
}
__device__ __forceinline__ ull dup2(float a) {
    ull r;
    asm("mov.b64 %0, {%1, %1};" : "=l"(r) : "f"(a));
    return r;
}
__device__ __forceinline__ void unpack2(ull v, float& lo, float& hi) {
    asm("mov.b64 {%0, %1}, %2;" : "=f"(lo), "=f"(hi) : "l"(v));
}

// ---- fast activations (MUFU; validated rel_err ~2e-6) ----
__device__ __forceinline__ float fsig(float x) {
    float e, r;
    asm("ex2.approx.f32 %0, %1;" : "=f"(e) : "f"(-1.4426950408889634f * x));
    asm("rcp.approx.f32 %0, %1;" : "=f"(r) : "f"(1.0f + e));
    return r;
}
__device__ __forceinline__ float ftanh(float x) {
    float e, r;
    asm("ex2.approx.f32 %0, %1;" : "=f"(e) : "f"(-2.8853900817779268f * x));
    asm("rcp.approx.f32 %0, %1;" : "=f"(r) : "f"(1.0f + e));
    return 2.0f * r - 1.0f;
}

// ---- packed GEMM over a 256-thread group; ltid = tid&255 ----
// kg = ltid>>2 (0..63 split-K), tr=(ltid>>1)&1, tc=ltid&1.
// Per k: 4 LDS.64 (W row-pairs) + 8 LDS.32 (A) + 8 dup + 32 FFMA2.
template <int NQ>
__device__ __forceinline__ void gemm_packed(const float* __restrict__ sWt,
                                            const float* __restrict__ sA,
                                            ull acc[4][8], int ltid) {
    const int kg = ltid >> 2;
    const int tr = (ltid >> 1) & 1;
    const int tc = ltid & 1;
    const float* wb = sWt + kg * WP + 8 * tr;
    const float* ab = sA + (8 * tc) * PA + kg;

#pragma unroll 1
    for (int q = 0; q < NQ; ++q) {
        const float* w = wb + q * (64 * WP);
        const float* a = ab + q * 64;
        float av[8];
#pragma unroll
        for (int j = 0; j < 8; ++j) av[j] = a[j * PA];
        ull ad[8];
#pragma unroll
        for (int j = 0; j < 8; ++j) ad[j] = dup2(av[j]);
        ull wv[4];
#pragma unroll
        for (int rp = 0; rp < 4; ++rp) wv[rp] = *(const ull*)(w + 2 * rp);
#pragma unroll
        for (int rp = 0; rp < 4; ++rp)
#pragma unroll
            for (int j = 0; j < 8; ++j)
                ffma2(acc[rp][j], wv[rp], ad[j]);
    }
}

// 3-level xor-shuffle (kg within warp) -> warp slab (col-major, pitch SP)
__device__ __forceinline__ void reduce_store(ull acc[4][8],
                                             float* __restrict__ slab,
                                             int ltid) {
    const int lane = ltid & 31;
    const int tr = (ltid >> 1) & 1;
    const int tc = ltid & 1;
    const bool st = (lane & 28) == 0;
#pragma unroll
    for (int rp = 0; rp < 4; ++rp)
#pragma unroll
        for (int j = 0; j < 8; ++j) {
            float lo, hi;
            unpack2(acc[rp][j], lo, hi);
            lo += __shfl_xor_sync(0xffffffffu, lo, 4);
            hi += __shfl_xor_sync(0xffffffffu, hi, 4);
            lo += __shfl_xor_sync(0xffffffffu, lo, 8);
            hi += __shfl_xor_sync(0xffffffffu, hi, 8);
            lo += __shfl_xor_sync(0xffffffffu, lo, 16);
            hi += __shfl_xor_sync(0xffffffffu, hi, 16);
            if (st) {
                float* d = slab + (8 * tc + j) * SP + 8 * tr + 2 * rp;
                d[0] = lo;
                d[1] = hi;
            }
        }
}

#define BARA() asm volatile("bar.sync 1, 256;" ::: "memory")
#define BARB() asm volatile("bar.sync 2, 256;" ::: "memory")

__global__ void __launch_bounds__(NTHREADS, 1)
lstm2_persistent(const float* __restrict__ x,
                 const float* __restrict__ W0,
                 const float* __restrict__ b0,
                 const float* __restrict__ W1,
                 const float* __restrict__ b1,
                 float* __restrict__ out) {
    extern __shared__ float smem[];
    float* sW0t = smem;                     // 768*18
    float* sW1t = sW0t + K0 * WP;           // 1024*18
    float* sA   = sW1t + K1 * WP;           // 16*1282  [x | h0 | h1]
    float* sSlA = sA + BATCH * PA;          // 8*320  group A slabs
    float* sSlB = sSlA + 8 * SLABSZ;        // 8*320  group B slabs
    float* sB0  = sSlB + 8 * SLABSZ;        // 16
    float* sB1  = sB0 + 16;                 // 16
    volatile int* sMail = (volatile int*)(sB1 + 16);  // [0]=h0Ready [1]=slotFree

    const int m    = blockIdx.x;
    const int tid  = threadIdx.x;
    const int ltid = tid & 255;
    const int grp  = tid >> 8;              // 0 = A, 1 = B
    const int u0   = m * UNITS;

    // ---- one-time setup (all 512 threads) ----
    for (int idx = tid; idx < ROWS * K0; idx += NTHREADS) {
        int r = idx / K0, k = idx % K0;
        int gg = r & 3, u = r >> 2;
        sW0t[k * WP + r] = W0[(size_t)(gg * HDIM + u0 + u) * K0 + k];
    }
    for (int idx = tid; idx < ROWS * K1; idx += NTHREADS) {
        int r = idx / K1, k = idx % K1;
        int gg = r & 3, u = r >> 2;
        sW1t[k * WP + r] = W1[(size_t)(gg * HDIM + u0 + u) * K1 + k];
    }
    if (tid < ROWS) {
        int gg = tid & 3, u = tid >> 2;
        sB0[tid] = b0[gg * HDIM + u0 + u];
        sB1[tid] = b1[gg * HDIM + u0 + u];
    }
    if (tid == 0) { sMail[0] = -1; sMail[1] = -1; }

    const int uu = ltid >> 4;               // cell role (ltid < 64)
    const int bb = ltid & 15;
    float c0 = 0.f, c1 = 0.f, h0r = 0.f, h1r = 0.f;

    const unsigned int fbase = g_f0[m];     // replay-safe (== g_f1[m])

    if (tid < 64) g_h0[1][bb * HDIM + u0 + uu] = 0.f;          // h0(-1)
    if (grp == 1 && ltid < 64) g_h1[1][bb * HDIM + u0 + uu] = 0.f;  // h1(-1)
    entry_barrier();

    ull acc[4][8];

    if (grp == 0) {
        // ================= GROUP A: h0 recurrence =================
        for (int i = 0; i <= SEQ; ++i) {
            const unsigned int seq = fbase + (unsigned)i;

            // stage x(i)
            if (i < SEQ) {
                const float* xrow = x + (size_t)i * IDIM;
                for (int idx = ltid; idx < BATCH * (IDIM / 2); idx += 256) {
                    int b = idx >> 7, k = (idx & 127) * 2;
                    *(float2*)(sA + b * PA + k) =
                        *(const float2*)(xrow + (size_t)b * SEQ * IDIM + k);
                }
            }
            // hot poll h0(i-1) + slot-free from B
            if (ltid < 128) {
                while ((int)(ld_acq(&g_f0[ltid]) - seq) < 0) { }
            } else if (ltid == 128 && i >= 2) {
                while (sMail[1] < i - 1) { }
            }
            BARA();
            // stage h0(i-1) into slot
            {
                const float* src = g_h0[(i + 1) & 1];
                for (int idx = ltid; idx < BATCH * (HDIM / 2); idx += 256) {
                    int b = idx >> 8, k = (idx & 255) * 2;
                    float2 v = __ldcg((const float2*)(src + b * HDIM + k));
                    *(float2*)(sA + b * PA + IDIM + k) = v;
                }
            }
            BARA();
            if (ltid == 0) sMail[0] = i;            // h0 slot ready
            // GEMM0 + cell0
            if (i < SEQ) {
#pragma unroll
                for (int a = 0; a < 4; ++a)
#pragma unroll
                    for (int b = 0; b < 8; ++b) acc[a][b] = 0ull;
                gemm_packed<12>(sW0t, sA, acc, ltid);
                reduce_store(acc, sSlA + (ltid >> 5) * SLABSZ, ltid);
                BARA();
                if (ltid < 64) {
                    const float* base = sSlA + bb * SP + 4 * uu;
                    float4 s = *(const float4*)(sB0 + 4 * uu);
#pragma unroll
                    for (int w = 0; w < 8; ++w) {
                        float4 v = *(const float4*)(base + w * SLABSZ);
                        s.x += v.x; s.y += v.y; s.z += v.z; s.w += v.w;
                    }
                    float ig = fsig(s.x), fg = fsig(s.y);
                    float cg = ftanh(s.z), og = fsig(s.w);
                    c0  = fg * c0 + ig * cg;
                    h0r = og * ftanh(c0);
                    g_h0[i & 1][bb * HDIM + u0 + uu] = h0r;
                    asm volatile("bar.sync 5, 64;" ::: "memory");
                    if (ltid == 0) st_rel(&g_f0[m], seq + 1u);
                }
            }
        }
        if (ltid < 64) {
            const size_t OH = (size_t)BATCH * SEQ * HDIM;
            const size_t BH = (size_t)BATCH * HDIM;
            const size_t o  = (size_t)bb * HDIM + u0 + uu;
            out[OH + 0 * BH + o] = h0r;     // h layer 0
            out[OH + 2 * BH + o] = c0;      // c layer 0
        }
    } else {
        // ================= GROUP B: layer 1 =================
        for (int i = 1; i <= SEQ; ++i) {
            const unsigned int seq = fbase + (unsigned)i;

            // cold poll h1(i-2)
            if (ltid < 128) {
                while ((int)(ld_acq(&g_f1[ltid]) - (seq - 1u)) < 0) { }
            }
            BARB();
            // stage h1(i-2)
            {
                const float* src = g_h1[i & 1];
                for (int idx = ltid; idx < BATCH * (HDIM / 2); idx += 256) {
                    int b = idx >> 8, k = (idx & 255) * 2;
                    float2 v = __ldcg((const float2*)(src + b * HDIM + k));
                    *(float2*)(sA + b * PA + IDIM + HDIM + k) = v;
                }
            }
            if (ltid == 0) { while (sMail[0] < i) { } }  // h0 slot ready?
            BARB();
            // GEMM1 part 1: h0 half (k 0..511) -- then release the slot
#pragma unroll
            for (int a = 0; a < 4; ++a)
#pragma unroll
                for (int b = 0; b < 8; ++b) acc[a][b] = 0ull;
            gemm_packed<8>(sW1t, sA + IDIM, acc, ltid);
            BARB();                                   // all h0 reads done
            if (ltid == 0) sMail[1] = i;              // slot free for A
            // GEMM1 part 2: h1 half (k 512..1023)
            gemm_packed<8>(sW1t + HDIM * WP, sA + IDIM + HDIM, acc, ltid);
            reduce_store(acc, sSlB + (ltid >> 5) * SLABSZ, ltid);
            BARB();
            // cell1 + publish h1(i-1) + out
            if (ltid < 64) {
                const float* base = sSlB + bb * SP + 4 * uu;
                float4 s = *(const float4*)(sB1 + 4 * uu);
#pragma unroll
                for (int w = 0; w < 8; ++w) {
                    float4 v = *(const float4*)(base + w * SLABSZ);
                    s.x += v.x; s.y += v.y; s.z += v.z; s.w += v.w;
                }
                float ig = fsig(s.x), fg = fsig(s.y);
                float cg = ftanh(s.z), og = fsig(s.w);
                c1  = fg * c1 + ig * cg;
                h1r = og * ftanh(c1);
                g_h1[(i - 1) & 1][bb * HDIM + u0 + uu] = h1r;
                out[((size_t)bb * SEQ + (i - 1)) * HDIM + u0 + uu] = h1r;
                asm volatile("bar.sync 6, 64;" ::: "memory");
                if (ltid == 0) st_rel(&g_f1[m], seq);
            }
        }
        if (ltid < 64) {
            const size_t OH = (size_t)BATCH * SEQ * HDIM;
            const size_t BH = (size_t)BATCH * HDIM;
            const size_t o  = (size_t)bb * HDIM + u0 + uu;
            out[OH + 1 * BH + o] = h1r;     // h layer 1
            out[OH + 3 * BH + o] = c1;      // c layer 1
        }
    }
}

extern "C" void kernel_launch(void* const* d_in, const int* in_sizes, int n_in,
                              void* d_out, int out_size) {
    const float* x  = (const float*)d_in[0];
    const float* W0 = (const float*)d_in[1];
    const float* b0 = (const float*)d_in[2];
    const float* W1 = (const float*)d_in[3];
    const float* b1 = (const float*)d_in[4];
    float* out = (float*)d_out;

    const int smem_floats = K0 * WP + K1 * WP + BATCH * PA +
                            2 * 8 * SLABSZ + 32 + 8;
    const int smem_bytes = smem_floats * (int)sizeof(float);  // 231,840 B

    cudaFuncSetAttribute(lstm2_persistent,
                         cudaFuncAttributeMaxDynamicSharedMemorySize,
                         smem_bytes);

    lstm2_persistent<<<NCTA, NTHREADS, smem_bytes>>>(x, W0, b0, W1, b1, out);
}

// round 16
// speedup vs baseline: 1.4716x; 1.4523x over previous
#include <cuda_runtime.h>
#include <math.h>

// ---------------------------------------------------------------------------
// 2-layer LSTM, B=16, S=2048, I=256, H=512, fp32.
// Persistent kernel, 128 CTAs (1/SM), 512 threads = 2 warp groups.
//   Group A (tid 0..255):  h0 recurrence: poll cnt0 -> stage [x|h0] -> GEMM0
//                          -> cell0 -> publish (red.add cnt0).
//   Group B (tid 256..511): GEMM1 (h0-half, signal slot-free, h1-half)
//                          -> cell1 -> publish cnt1 -> out.
// R15: flag ARRAYS replaced by aggregated arrival COUNTERS.
//   - publish: one red.release.gpu.add per CTA (no read traffic)
//   - wait: ONE poller thread per CTA on one counter line, nanosleep backoff
//   -> chip-wide poll traffic cut >100x (was ~50 GB/run hammering 4 L2 lines)
// Packed row-pair GEMM (k-major W, FFMA2 over 2 rows), MUFU activations.
// ---------------------------------------------------------------------------

#define BATCH 16
#define SEQ   2048
#define IDIM  256
#define HDIM  512
#define NCTA  128
#define NTHREADS 512
#define ROWS  16
#define UNITS 4
#define K0    768
#define K1    1024
#define WP    18          // k-major weight pitch
#define PA    1282        // A pitch [x:256 | h0:512 | h1:512]
#define SP    20          // slab pitch (col-major)
#define SLABSZ (16*SP)    // 320 floats per warp slab

typedef unsigned long long ull;

// ---- global scratch ----
__device__ __align__(16) float g_h0[2][BATCH * HDIM];
__device__ __align__(16) float g_h1[2][BATCH * HDIM];
__device__ unsigned int g_cnt0[2];      // arrival counters, NEVER reset
__device__ unsigned int g_cnt1[2];      // (monotone across graph replays)
__device__ unsigned int g_bar_count = 0;
__device__ volatile unsigned int g_bar_epoch = 0;

__device__ __forceinline__ unsigned int ld_acq(const unsigned int* p) {
    unsigned int v;
    asm volatile("ld.acquire.gpu.u32 %0, [%1];" : "=r"(v) : "l"(p) : "memory");
    return v;
}
__device__ __forceinline__ void red_rel_add(unsigned int* p, unsigned int v) {
    asm volatile("red.release.gpu.global.add.u32 [%0], %1;"
                 :: "l"(p), "r"(v) : "memory");
}
// single-thread poll with backoff: waits until *c - tgt >= 0 (mod 2^32)
__device__ __forceinline__ void poll_cnt(unsigned int* c, unsigned int tgt) {
    while ((int)(ld_acq(c) - tgt) < 0) { __nanosleep(32); }
}

__device__ __forceinline__ void entry_barrier() {
    unsigned int ebase = 0;
    if (threadIdx.x == 0) ebase = g_bar_epoch;
    __syncthreads();
    if (threadIdx.x == 0) {
        __threadfence();
        unsigned int a = atomicAdd(&g_bar_count, 1u);
        unsigned int target = ebase + 1;
        if (a == NCTA - 1) {
            atomicExch(&g_bar_count, 0u);
            __threadfence();
            g_bar_epoch = target;
        } else {
            while ((int)(g_bar_epoch - target) < 0) { }
        }
        __threadfence();
    }
    __syncthreads();
}

// ---- packed f32x2 helpers ----
__device__ __forceinline__ void ffma2(ull& acc, ull a, ull b) {
    asm("fma.rn.f32x2 %0, %1, %2, %0;" : "+l"(acc) : "l"(a), "l"(b));
}
__device__ __forceinline__ ull dup2(float a) {
    ull r;
    asm("mov.b64 %0, {%1, %1};" : "=l"(r) : "f"(a));
    return r;
}
__device__ __forceinline__ void unpack2(ull v, float& lo, float& hi) {
    asm("mov.b64 {%0, %1}, %2;" : "=f"(lo), "=f"(hi) : "l"(v));
}

// ---- fast activations (MUFU; validated rel_err ~2e-6) ----
__device__ __forceinline__ float fsig(float x) {
    float e, r;
    asm("ex2.approx.f32 %0, %1;" : "=f"(e) : "f"(-1.4426950408889634f * x));
    asm("rcp.approx.f32 %0, %1;" : "=f"(r) : "f"(1.0f + e));
    return r;
}
__device__ __forceinline__ float ftanh(float x) {
    float e, r;
    asm("ex2.approx.f32 %0, %1;" : "=f"(e) : "f"(-2.8853900817779268f * x));
    asm("rcp.approx.f32 %0, %1;" : "=f"(r) : "f"(1.0f + e));
    return 2.0f * r - 1.0f;
}

// ---- packed GEMM over a 256-thread group; ltid = tid&255 ----
template <int NQ>
__device__ __forceinline__ void gemm_packed(const float* __restrict__ sWt,
                                            const float* __restrict__ sA,
                                            ull acc[4][8], int ltid) {
    const int kg = ltid >> 2;
    const int tr = (ltid >> 1) & 1;
    const int tc = ltid & 1;
    const float* wb = sWt + kg * WP + 8 * tr;
    const float* ab = sA + (8 * tc) * PA + kg;

#pragma unroll 1
    for (int q = 0; q < NQ; ++q) {
        const float* w = wb + q * (64 * WP);
        const float* a = ab + q * 64;
        float av[8];
#pragma unroll
        for (int j = 0; j < 8; ++j) av[j] = a[j * PA];
        ull ad[8];
#pragma unroll
        for (int j = 0; j < 8; ++j) ad[j] = dup2(av[j]);
        ull wv[4];
#pragma unroll
        for (int rp = 0; rp < 4; ++rp) wv[rp] = *(const ull*)(w + 2 * rp);
#pragma unroll
        for (int rp = 0; rp < 4; ++rp)
#pragma unroll
            for (int j = 0; j < 8; ++j)
                ffma2(acc[rp][j], wv[rp], ad[j]);
    }
}

__device__ __forceinline__ void reduce_store(ull acc[4][8],
                                             float* __restrict__ slab,
                                             int ltid) {
    const int lane = ltid & 31;
    const int tr = (ltid >> 1) & 1;
    const int tc = ltid & 1;
    const bool st = (lane & 28) == 0;
#pragma unroll
    for (int rp = 0; rp < 4; ++rp)
#pragma unroll
        for (int j = 0; j < 8; ++j) {
            float lo, hi;
            unpack2(acc[rp][j], lo, hi);
            lo += __shfl_xor_sync(0xffffffffu, lo, 4);
            hi += __shfl_xor_sync(0xffffffffu, hi, 4);
            lo += __shfl_xor_sync(0xffffffffu, lo, 8);
            hi += __shfl_xor_sync(0xffffffffu, hi, 8);
            lo += __shfl_xor_sync(0xffffffffu, lo, 16);
            hi += __shfl_xor_sync(0xffffffffu, hi, 16);
            if (st) {
                float* d = slab + (8 * tc + j) * SP + 8 * tr + 2 * rp;
                d[0] = lo;
                d[1] = hi;
            }
        }
}

#define BARA() asm volatile("bar.sync 1, 256;" ::: "memory")
#define BARB() asm volatile("bar.sync 2, 256;" ::: "memory")

__global__ void __launch_bounds__(NTHREADS, 1)
lstm2_persistent(const float* __restrict__ x,
                 const float* __restrict__ W0,
                 const float* __restrict__ b0,
                 const float* __restrict__ W1,
                 const float* __restrict__ b1,
                 float* __restrict__ out) {
    extern __shared__ float smem[];
    float* sW0t = smem;                     // 768*18
    float* sW1t = sW0t + K0 * WP;           // 1024*18
    float* sA   = sW1t + K1 * WP;           // 16*1282  [x | h0 | h1]
    float* sSlA = sA + BATCH * PA;          // 8*320
    float* sSlB = sSlA + 8 * SLABSZ;        // 8*320
    float* sB0  = sSlB + 8 * SLABSZ;        // 16
    float* sB1  = sB0 + 16;                 // 16
    volatile int* sMail = (volatile int*)(sB1 + 16);  // [0]=h0Ready [1]=slotFree

    const int m    = blockIdx.x;
    const int tid  = threadIdx.x;
    const int ltid = tid & 255;
    const int grp  = tid >> 8;              // 0 = A, 1 = B
    const int u0   = m * UNITS;

    // ---- one-time setup ----
    for (int idx = tid; idx < ROWS * K0; idx += NTHREADS) {
        int r = idx / K0, k = idx % K0;
        int gg = r & 3, u = r >> 2;
        sW0t[k * WP + r] = W0[(size_t)(gg * HDIM + u0 + u) * K0 + k];
    }
    for (int idx = tid; idx < ROWS * K1; idx += NTHREADS) {
        int r = idx / K1, k = idx % K1;
        int gg = r & 3, u = r >> 2;
        sW1t[k * WP + r] = W1[(size_t)(gg * HDIM + u0 + u) * K1 + k];
    }
    if (tid < ROWS) {
        int gg = tid & 3, u = tid >> 2;
        sB0[tid] = b0[gg * HDIM + u0 + u];
        sB1[tid] = b1[gg * HDIM + u0 + u];
    }
    if (tid == 0) { sMail[0] = -1; sMail[1] = -1; }

    const int uu = ltid >> 4;               // cell role (ltid < 64)
    const int bb = ltid & 15;
    float c0 = 0.f, c1 = 0.f, h0r = 0.f, h1r = 0.f;

    // counter bases (read BEFORE entry barrier; no increments until after)
    const unsigned int c0b[2] = { g_cnt0[0], g_cnt0[1] };
    const unsigned int c1b[2] = { g_cnt1[0], g_cnt1[1] };

    if (tid < 64) g_h0[1][bb * HDIM + u0 + uu] = 0.f;               // h0(-1)
    if (grp == 1 && ltid < 64) g_h1[1][bb * HDIM + u0 + uu] = 0.f;  // h1(-1)
    entry_barrier();

    ull acc[4][8];

    if (grp == 0) {
        // ================= GROUP A: h0 recurrence =================
        for (int i = 0; i <= SEQ; ++i) {
            // stage x(i)
            if (i < SEQ) {
                const float* xrow = x + (size_t)i * IDIM;
                for (int idx = ltid; idx < BATCH * (IDIM / 2); idx += 256) {
                    int b = idx >> 7, k = (idx & 127) * 2;
                    *(float2*)(sA + b * PA + k) =
                        *(const float2*)(xrow + (size_t)b * SEQ * IDIM + k);
                }
            }
            // hot wait: h0(i-1) published by ALL CTAs (single poller)
            if (i > 0 && ltid == 0) {
                const int j = i - 1;
                poll_cnt(&g_cnt0[j & 1],
                         c0b[j & 1] + ((unsigned)(j >> 1) + 1u) * NCTA);
            }
            // slot-free from B (B done reading h0(i-2) from sA)
            if (ltid == 128 && i >= 2) {
                while (sMail[1] < i - 1) { }
            }
            BARA();
            // stage h0(i-1) into sA slot
            {
                const float* src = g_h0[(i + 1) & 1];
                for (int idx = ltid; idx < BATCH * (HDIM / 2); idx += 256) {
                    int b = idx >> 8, k = (idx & 255) * 2;
                    float2 v = __ldcg((const float2*)(src + b * HDIM + k));
                    *(float2*)(sA + b * PA + IDIM + k) = v;
                }
            }
            BARA();
            if (ltid == 0) sMail[0] = i;            // h0 slot ready for B
            // GEMM0 + cell0
            if (i < SEQ) {
#pragma unroll
                for (int a = 0; a < 4; ++a)
#pragma unroll
                    for (int b = 0; b < 8; ++b) acc[a][b] = 0ull;
                gemm_packed<12>(sW0t, sA, acc, ltid);
                reduce_store(acc, sSlA + (ltid >> 5) * SLABSZ, ltid);
                BARA();
                if (ltid < 64) {
                    const float* base = sSlA + bb * SP + 4 * uu;
                    float4 s = *(const float4*)(sB0 + 4 * uu);
#pragma unroll
                    for (int w = 0; w < 8; ++w) {
                        float4 v = *(const float4*)(base + w * SLABSZ);
                        s.x += v.x; s.y += v.y; s.z += v.z; s.w += v.w;
                    }
                    float ig = fsig(s.x), fg = fsig(s.y);
                    float cg = ftanh(s.z), og = fsig(s.w);
                    c0  = fg * c0 + ig * cg;
                    h0r = og * ftanh(c0);
                    g_h0[i & 1][bb * HDIM + u0 + uu] = h0r;
                    asm volatile("bar.sync 5, 64;" ::: "memory");
                    if (ltid == 0) red_rel_add(&g_cnt0[i & 1], 1u); // publish
                }
            }
        }
        if (ltid < 64) {
            const size_t OH = (size_t)BATCH * SEQ * HDIM;
            const size_t BH = (size_t)BATCH * HDIM;
            const size_t o  = (size_t)bb * HDIM + u0 + uu;
            out[OH + 0 * BH + o] = h0r;     // h layer 0
            out[OH + 2 * BH + o] = c0;      // c layer 0
        }
    } else {
        // ================= GROUP B: layer 1 =================
        for (int i = 1; i <= SEQ; ++i) {
            // cold wait: h1(i-2) published by ALL CTAs
            if (i >= 2 && ltid == 0) {
                const int j = i - 2;
                poll_cnt(&g_cnt1[j & 1],
                         c1b[j & 1] + ((unsigned)(j >> 1) + 1u) * NCTA);
            }
            BARB();
            // stage h1(i-2)
            {
                const float* src = g_h1[i & 1];
                for (int idx = ltid; idx < BATCH * (HDIM / 2); idx += 256) {
                    int b = idx >> 8, k = (idx & 255) * 2;
                    float2 v = __ldcg((const float2*)(src + b * HDIM + k));
                    *(float2*)(sA + b * PA + IDIM + HDIM + k) = v;
                }
            }
            if (ltid == 0) { while (sMail[0] < i) { } }  // h0 slot ready?
            BARB();
            // GEMM1 part 1: h0 half (k 0..511), then release the slot
#pragma unroll
            for (int a = 0; a < 4; ++a)
#pragma unroll
                for (int b = 0; b < 8; ++b) acc[a][b] = 0ull;
            gemm_packed<8>(sW1t, sA + IDIM, acc, ltid);
            BARB();                                   // all h0 reads done
            if (ltid == 0) sMail[1] = i;              // slot free for A
            // GEMM1 part 2: h1 half (k 512..1023)
            gemm_packed<8>(sW1t + HDIM * WP, sA + IDIM + HDIM, acc, ltid);
            reduce_store(acc, sSlB + (ltid >> 5) * SLABSZ, ltid);
            BARB();
            // cell1 + publish h1(i-1) + out
            if (ltid < 64) {
                const float* base = sSlB + bb * SP + 4 * uu;
                float4 s = *(const float4*)(sB1 + 4 * uu);
#pragma unroll
                for (int w = 0; w < 8; ++w) {
                    float4 v = *(const float4*)(base + w * SLABSZ);
                    s.x += v.x; s.y += v.y; s.z += v.z; s.w += v.w;
                }
                float ig = fsig(s.x), fg = fsig(s.y);
                float cg = ftanh(s.z), og = fsig(s.w);
                c1  = fg * c1 + ig * cg;
                h1r = og * ftanh(c1);
                g_h1[(i - 1) & 1][bb * HDIM + u0 + uu] = h1r;
                out[((size_t)bb * SEQ + (i - 1)) * HDIM + u0 + uu] = h1r;
                asm volatile("bar.sync 6, 64;" ::: "memory");
                if (ltid == 0) red_rel_add(&g_cnt1[(i - 1) & 1], 1u);
            }
        }
        if (ltid < 64) {
            const size_t OH = (size_t)BATCH * SEQ * HDIM;
            const size_t BH = (size_t)BATCH * HDIM;
            const size_t o  = (size_t)bb * HDIM + u0 + uu;
            out[OH + 1 * BH + o] = h1r;     // h layer 1
            out[OH + 3 * BH + o] = c1;      // c layer 1
        }
    }
}

extern "C" void kernel_launch(void* const* d_in, const int* in_sizes, int n_in,
                              void* d_out, int out_size) {
    const float* x  = (const float*)d_in[0];
    const float* W0 = (const float*)d_in[1];
    const float* b0 = (const float*)d_in[2];
    const float* W1 = (const float*)d_in[3];
    const float* b1 = (const float*)d_in[4];
    float* out = (float*)d_out;

    const int smem_floats = K0 * WP + K1 * WP + BATCH * PA +
                            2 * 8 * SLABSZ + 32 + 8;
    const int smem_bytes = smem_floats * (int)sizeof(float);  // ~231.8 KB

    cudaFuncSetAttribute(lstm2_persistent,
                         cudaFuncAttributeMaxDynamicSharedMemorySize,
                         smem_bytes);

    lstm2_persistent<<<NCTA, NTHREADS, smem_bytes>>>(x, W0, b0, W1, b1, out);
}